// round 7
// baseline (speedup 1.0000x reference)
#include <cuda_runtime.h>
#include <cuda_bf16.h>
#include <cstdint>

// f_z[b,i] = z[b,i] + sum_{j<i} h[b, i*(i-1)/2 + j] * z[b,j]
// h packed strictly-lower-triangular row-major. HBM-streaming bound.
//
// Warp handles row pair (i, 511-i) (perfect balance). h read as
// aligned-DOWN predicated LDG.128 quads (no scalar edge loads). z kept in
// shared as FOUR pre-shifted zero-padded copies Z_m[j] = z[j-m], so h-quad v
// of a row with offset%4==m pairs with one aligned LDS.128 from Z_m[4v..].
// Head junk hits the zero padding; tail junk (<=3 comps of one quad) is
// zeroed in registers.

#define DIM 512
#define HLEN ((DIM * (DIM - 1)) / 2)   // 130816
#define THREADS 256
#define ZPAD 640                        // per-copy stride; covers reads to idx 639
#define FULL 0xffffffffu

__global__ __launch_bounds__(THREADS) void LinearMap_kernel(
    const float* __restrict__ z,
    const float* __restrict__ h,
    float* __restrict__ out,
    int out_size)
{
    __shared__ float zsh[4 * ZPAD];     // Z_m at m*ZPAD; Z_0 == plain z

    const int b    = blockIdx.x >> 5;   // / 32
    const int pg   = blockIdx.x & 31;
    const int tid  = threadIdx.x;
    const int warp = tid >> 5;
    const int lane = tid & 31;

    const float* zb = z + (size_t)b * DIM;
    #pragma unroll
    for (int m = 0; m < 4; ++m)
        for (int j = tid; j < ZPAD; j += THREADS) {
            int src = j - m;
            zsh[m * ZPAD + j] = (src >= 0 && src < DIM) ? zb[src] : 0.f;
        }
    __syncthreads();

    const int ia = pg * 8 + warp;              // 0..255
    const int ib = DIM - 1 - ia;               // 256..511
    const unsigned offa = (unsigned)(ia * (ia - 1) / 2);
    const unsigned offb = (unsigned)(ib * (ib - 1) / 2);
    const int misa = (int)(offa & 3u), misb = (int)(offb & 3u);

    const float* hbase = h + (size_t)b * HLEN;
    const float4* ha4 = (const float4*)(hbase + (offa & ~3u));
    const float4* hq4 = (const float4*)(hbase + (offb & ~3u));

    const int ea = ia + misa, eb = ib + misb;  // valid elems are [mis, e)
    const int nqa = (ea + 3) >> 2;             // <= 65  -> 3 steps
    const int nqb = (eb + 3) >> 2;             // <= 129 -> 5 steps
    const int vba = ea >> 2, ca = ea & 3;      // partial tail quad / count
    const int vbb = eb >> 2, cb = eb & 3;

    // ---- front-batched independent predicated loads ----
    float4 B0, B1, B2, B3, B4, A0, A1, A2;
    {
        const float4 zf = make_float4(0.f, 0.f, 0.f, 0.f);
        B0 = (lane       < nqb) ? __ldcs(hq4 + lane)       : zf;
        B1 = (lane + 32  < nqb) ? __ldcs(hq4 + lane + 32)  : zf;
        B2 = (lane + 64  < nqb) ? __ldcs(hq4 + lane + 64)  : zf;
        B3 = (lane + 96  < nqb) ? __ldcs(hq4 + lane + 96)  : zf;
        B4 = (lane + 128 < nqb) ? __ldcs(hq4 + lane + 128) : zf;
        A0 = (lane       < nqa) ? __ldcs(ha4 + lane)       : zf;
        A1 = (lane + 32  < nqa) ? __ldcs(ha4 + lane + 32)  : zf;
        A2 = (lane + 64  < nqa) ? __ldcs(ha4 + lane + 64)  : zf;
    }

    // ---- zero partial-tail components (junk h pairs with valid z) ----
    #define TAILFIX(Q, st, vb, c)                                   \
        if ((c) && (lane + 32 * (st)) == (vb)) {                    \
            if ((c) <= 1) Q.y = 0.f;                                \
            if ((c) <= 2) Q.z = 0.f;                                \
            Q.w = 0.f;                                              \
        }
    TAILFIX(A0, 0, vba, ca) TAILFIX(A1, 1, vba, ca) TAILFIX(A2, 2, vba, ca)
    TAILFIX(B0, 0, vbb, cb) TAILFIX(B1, 1, vbb, cb) TAILFIX(B2, 2, vbb, cb)
    TAILFIX(B3, 3, vbb, cb) TAILFIX(B4, 4, vbb, cb)
    #undef TAILFIX

    const float4* Za = (const float4*)(zsh + misa * ZPAD);
    const float4* Zb = (const float4*)(zsh + misb * ZPAD);

    float s0 = 0.f, s1 = 0.f, s2 = 0.f, s3 = 0.f;
    #define STEP(Q, Zp, st) {                                       \
        float4 zv = (Zp)[lane + 32 * (st)];                         \
        s0 = fmaf(Q.x, zv.x, s0);                                   \
        s1 = fmaf(Q.y, zv.y, s1);                                   \
        s2 = fmaf(Q.z, zv.z, s2);                                   \
        s3 = fmaf(Q.w, zv.w, s3);                                   \
    }
    STEP(B0, Zb, 0) STEP(B1, Zb, 1) STEP(B2, Zb, 2)
    STEP(B3, Zb, 3) STEP(B4, Zb, 4)
    float sumb = (s0 + s1) + (s2 + s3);

    s0 = s1 = s2 = s3 = 0.f;
    STEP(A0, Za, 0) STEP(A1, Za, 1) STEP(A2, Za, 2)
    float suma = (s0 + s1) + (s2 + s3);
    #undef STEP

    #pragma unroll
    for (int o = 16; o; o >>= 1) {
        suma += __shfl_xor_sync(FULL, suma, o);
        sumb += __shfl_xor_sync(FULL, sumb, o);
    }

    if (lane == 0) {
        float* ob = out + (size_t)b * DIM;
        ob[ia] = zsh[ia] + suma;    // Z_0 is plain z
        ob[ib] = zsh[ib] + sumb;
    }

    // logdet / tail zeroing (d_out is poisoned)
    if (blockIdx.x == 0) {
        const int nfz = (int)(gridDim.x >> 5) * DIM;
        for (int k = nfz + tid; k < out_size; k += THREADS) out[k] = 0.0f;
    }
}

extern "C" void kernel_launch(void* const* d_in, const int* in_sizes, int n_in,
                              void* d_out, int out_size)
{
    const float* z = (const float*)d_in[0];   // [batch, 512]
    const float* h = (const float*)d_in[1];   // [batch, 130816]
    float* out = (float*)d_out;

    const int batch = in_sizes[0] / DIM;      // 256

    dim3 grid(batch * 32);                    // 8192 identical CTAs
    LinearMap_kernel<<<grid, THREADS>>>(z, h, out, out_size);
}

// round 8
// speedup vs baseline: 1.3591x; 1.3591x over previous
#include <cuda_runtime.h>
#include <cuda_bf16.h>
#include <cstdint>

// f_z[b,i] = z[b,i] + sum_{j<i} h[b, i*(i-1)/2 + j] * z[b,j]
// h packed strictly-lower-triangular row-major. HBM-streaming bound.
//
// Warp handles row pair (i, 511-i) (perfect balance). h read as aligned-DOWN
// predicated LDG.128 quads. z in shared as 4 shifted zero-padded copies
// Z_m[j] = z[j-m]; h-quad v of a row with off%4==m pairs with ONE aligned
// LDS.128 from Z_m[4v..]. Head junk hits zero padding; tail junk (<=3
// products) is SUBTRACTED by the owning lane after accumulation (replaces
// R7's costly predicated register zeroing). Fill is 2 iters/thread.

#define DIM 512
#define HLEN ((DIM * (DIM - 1)) / 2)   // 130816
#define THREADS 256
#define ZPADF 640                       // floats per copy (16B-aligned stride)
#define FULL 0xffffffffu

__global__ __launch_bounds__(THREADS) void LinearMap_kernel(
    const float* __restrict__ z,
    const float* __restrict__ h,
    float* __restrict__ out,
    int out_size)
{
    __shared__ float zsh[4 * ZPADF];    // 10240 B; copy m at m*ZPADF

    const int b    = blockIdx.x >> 5;   // / 32
    const int pg   = blockIdx.x & 31;
    const int tid  = threadIdx.x;
    const int warp = tid >> 5;
    const int lane = tid & 31;

    // pass 1: zero the pad regions ([512,640) tails; [0,m) heads)
    {
        int m = tid >> 6;               // 0..3
        int j = 512 + (tid & 63);
        zsh[m * ZPADF + j]      = 0.f;
        zsh[m * ZPADF + j + 64] = 0.f;
        if (tid < 16) {
            int mm = tid >> 2, k = tid & 3;
            if (k < mm) zsh[mm * ZPADF + k] = 0.f;
        }
    }
    __syncthreads();
    // pass 2: valid data into all 4 shifted copies (overwrites pad overlap)
    {
        const float* zb = z + (size_t)b * DIM;
        #pragma unroll
        for (int j = tid; j < DIM; j += THREADS) {
            float v = zb[j];
            zsh[j]                 = v;   // Z_0
            zsh[ZPADF     + j + 1] = v;   // Z_1[j+1] = z[j]
            zsh[2 * ZPADF + j + 2] = v;
            zsh[3 * ZPADF + j + 3] = v;
        }
    }
    __syncthreads();

    const int ia = pg * 8 + warp;              // 0..255
    const int ib = DIM - 1 - ia;               // 256..511
    const unsigned offa = (unsigned)(ia * (ia - 1) / 2);
    const unsigned offb = (unsigned)(ib * (ib - 1) / 2);
    const int misa = (int)(offa & 3u), misb = (int)(offb & 3u);

    const float* hbase = h + (size_t)b * HLEN;
    const float4* ha4 = (const float4*)(hbase + (offa & ~3u));
    const float4* hq4 = (const float4*)(hbase + (offb & ~3u));

    const int ea = ia + misa, eb = ib + misb;  // valid padded elems: [misa,ea)
    const int nqa = (ea + 3) >> 2;             // <= 65  -> 3 steps
    const int nqb = (eb + 3) >> 2;             // <= 129 -> 5 steps

    // ---- front-batched independent predicated loads (zero-filled) ----
    const float4 zf = make_float4(0.f, 0.f, 0.f, 0.f);
    float4 B0 = (lane       < nqb) ? __ldcs(hq4 + lane)       : zf;
    float4 B1 = (lane + 32  < nqb) ? __ldcs(hq4 + lane + 32)  : zf;
    float4 B2 = (lane + 64  < nqb) ? __ldcs(hq4 + lane + 64)  : zf;
    float4 B3 = (lane + 96  < nqb) ? __ldcs(hq4 + lane + 96)  : zf;
    float4 B4 = (lane + 128 < nqb) ? __ldcs(hq4 + lane + 128) : zf;
    float4 A0 = (lane       < nqa) ? __ldcs(ha4 + lane)       : zf;
    float4 A1 = (lane + 32  < nqa) ? __ldcs(ha4 + lane + 32)  : zf;
    float4 A2 = (lane + 64  < nqa) ? __ldcs(ha4 + lane + 64)  : zf;

    const float4* Za = (const float4*)(zsh + misa * ZPADF);
    const float4* Zb = (const float4*)(zsh + misb * ZPADF);

    float s0 = 0.f, s1 = 0.f, s2 = 0.f, s3 = 0.f;
    #define STEP(Q, Zp, st) {                                   \
        float4 zv = (Zp)[lane + 32 * (st)];                     \
        s0 = fmaf(Q.x, zv.x, s0);                               \
        s1 = fmaf(Q.y, zv.y, s1);                               \
        s2 = fmaf(Q.z, zv.z, s2);                               \
        s3 = fmaf(Q.w, zv.w, s3);                               \
    }
    STEP(B0, Zb, 0) STEP(B1, Zb, 1) STEP(B2, Zb, 2)
    STEP(B3, Zb, 3) STEP(B4, Zb, 4)
    float sumb = (s0 + s1) + (s2 + s3);

    s0 = s1 = s2 = s3 = 0.f;
    STEP(A0, Za, 0) STEP(A1, Za, 1) STEP(A2, Za, 2)
    float suma = (s0 + s1) + (s2 + s3);
    #undef STEP

    // ---- subtract tail-junk products (components k>=c of quad e>>2) ----
    {
        const int cb = eb & 3;
        if (cb) {                               // warp-uniform
            const int vb = eb >> 2;
            if (lane == (vb & 31)) {
                const int st = vb >> 5;
                float4 Q = (st == 0) ? B0 : (st == 1) ? B1 :
                           (st == 2) ? B2 : (st == 3) ? B3 : B4;
                float4 zt = Zb[vb];
                float jnk = Q.w * zt.w;
                if (cb <= 2) jnk = fmaf(Q.z, zt.z, jnk);
                if (cb <= 1) jnk = fmaf(Q.y, zt.y, jnk);
                sumb -= jnk;
            }
        }
        const int ca = ea & 3;
        if (ca) {                               // warp-uniform
            const int va = ea >> 2;
            if (lane == (va & 31)) {
                const int st = va >> 5;
                float4 Q = (st == 0) ? A0 : (st == 1) ? A1 : A2;
                float4 zt = Za[va];
                float jnk = Q.w * zt.w;
                if (ca <= 2) jnk = fmaf(Q.z, zt.z, jnk);
                if (ca <= 1) jnk = fmaf(Q.y, zt.y, jnk);
                suma -= jnk;
            }
        }
    }

    #pragma unroll
    for (int o = 16; o; o >>= 1) {
        suma += __shfl_xor_sync(FULL, suma, o);
        sumb += __shfl_xor_sync(FULL, sumb, o);
    }

    if (lane == 0) {
        float* ob = out + (size_t)b * DIM;
        ob[ia] = zsh[ia] + suma;    // Z_0 is plain z
        ob[ib] = zsh[ib] + sumb;
    }

    // logdet / tail zeroing (d_out is poisoned)
    if (blockIdx.x == 0) {
        const int nfz = (int)(gridDim.x >> 5) * DIM;
        for (int k = nfz + tid; k < out_size; k += THREADS) out[k] = 0.0f;
    }
}

extern "C" void kernel_launch(void* const* d_in, const int* in_sizes, int n_in,
                              void* d_out, int out_size)
{
    const float* z = (const float*)d_in[0];   // [batch, 512]
    const float* h = (const float*)d_in[1];   // [batch, 130816]
    float* out = (float*)d_out;

    const int batch = in_sizes[0] / DIM;      // 256

    dim3 grid(batch * 32);                    // 8192 identical CTAs
    LinearMap_kernel<<<grid, THREADS>>>(z, h, out, out_size);
}

// round 9
// speedup vs baseline: 1.4651x; 1.0780x over previous
#include <cuda_runtime.h>
#include <cuda_bf16.h>
#include <cstdint>

// f_z[b,i] = z[b,i] + sum_{j<i} h[b, i*(i-1)/2 + j] * z[b,j]
// h packed strictly-lower-triangular row-major. Latency/issue-composite bound:
// winning recipe = high occupancy + minimal instructions per byte.
//
// Warp handles row pair (i, 511-i). h read as aligned-DOWN predicated
// LDG.128 quads in two waves (MLP>=4, low register footprint). z in shared
// as 4 shifted zero-padded copies Z_m[j] = z[j-m]: h-quad v of a row with
// off%4==m pairs with ONE aligned LDS.128 from Z_m[4v..] (conflict-free).
// Head junk hits zero padding; tail junk is zeroed IN the h register before
// use (quads die at their FMA -> low live-register count).

#define DIM 512
#define HLEN ((DIM * (DIM - 1)) / 2)   // 130816
#define THREADS 256
#define ZPADF 640                       // floats per shifted copy
#define FULL 0xffffffffu

__global__ __launch_bounds__(THREADS, 6) void LinearMap_kernel(
    const float* __restrict__ z,
    const float* __restrict__ h,
    float* __restrict__ out,
    int out_size)
{
    __shared__ float zsh[4 * ZPADF];    // copy m at m*ZPADF

    const int b    = blockIdx.x >> 5;   // / 32
    const int pg   = blockIdx.x & 31;
    const int tid  = threadIdx.x;
    const int warp = tid >> 5;
    const int lane = tid & 31;

    // pass 1: zero pad regions ([512,640) per copy; heads [0,m))
    {
        int m = tid >> 6;               // 0..3
        int j = 512 + (tid & 63);
        zsh[m * ZPADF + j]      = 0.f;
        zsh[m * ZPADF + j + 64] = 0.f;
        if (tid < 16) {
            int mm = tid >> 2, k = tid & 3;
            if (k < mm) zsh[mm * ZPADF + k] = 0.f;
        }
    }
    __syncthreads();
    // pass 2: data into all 4 shifted copies
    {
        const float* zb = z + (size_t)b * DIM;
        #pragma unroll
        for (int j = tid; j < DIM; j += THREADS) {
            float v = zb[j];
            zsh[j]                 = v;
            zsh[ZPADF     + j + 1] = v;
            zsh[2 * ZPADF + j + 2] = v;
            zsh[3 * ZPADF + j + 3] = v;
        }
    }
    __syncthreads();

    const int ia = pg * 8 + warp;              // 0..255
    const int ib = DIM - 1 - ia;               // 256..511
    const unsigned offa = (unsigned)(ia * (ia - 1) / 2);
    const unsigned offb = (unsigned)(ib * (ib - 1) / 2);
    const int misa = (int)(offa & 3u), misb = (int)(offb & 3u);

    const float* hbase = h + (size_t)b * HLEN;
    const float4* ha4 = (const float4*)(hbase + (offa & ~3u));
    const float4* hq4 = (const float4*)(hbase + (offb & ~3u));

    const int ea = ia + misa, eb = ib + misb;  // valid elems: [mis, e)
    const int nqa = (ea + 3) >> 2;             // <= 65
    const int nqb = (eb + 3) >> 2;             // <= 129
    const int vba = ea >> 2, ca = ea & 3;      // partial tail quad / count
    const int vbb = eb >> 2, cb = eb & 3;

    const float4* Za = (const float4*)(zsh + misa * ZPADF);
    const float4* Zb = (const float4*)(zsh + misb * ZPADF);
    const float4 zf = make_float4(0.f, 0.f, 0.f, 0.f);

    // zero invalid tail components so the quad can be used unguarded
    #define TAILFIX(Q, st, vb, c)                               \
        if ((c) && (lane + 32 * (st)) == (vb)) {                \
            if ((c) <= 1) Q.y = 0.f;                            \
            if ((c) <= 2) Q.z = 0.f;                            \
            Q.w = 0.f;                                          \
        }
    #define STEP(Q, Zp, st) {                                   \
        float4 zv = (Zp)[lane + 32 * (st)];                     \
        s0 = fmaf(Q.x, zv.x, s0);                               \
        s1 = fmaf(Q.y, zv.y, s1);                               \
        s2 = fmaf(Q.z, zv.z, s2);                               \
        s3 = fmaf(Q.w, zv.w, s3);                               \
    }

    float s0 = 0.f, s1 = 0.f, s2 = 0.f, s3 = 0.f;

    // ---- wave 1: 4 quads of row b ----
    float4 B0 = (lane       < nqb) ? __ldcs(hq4 + lane)       : zf;
    float4 B1 = (lane + 32  < nqb) ? __ldcs(hq4 + lane + 32)  : zf;
    float4 B2 = (lane + 64  < nqb) ? __ldcs(hq4 + lane + 64)  : zf;
    float4 B3 = (lane + 96  < nqb) ? __ldcs(hq4 + lane + 96)  : zf;
    TAILFIX(B0, 0, vbb, cb) TAILFIX(B1, 1, vbb, cb)
    STEP(B0, Zb, 0) STEP(B1, Zb, 1)

    // ---- wave 2: last b quad + row a ----
    float4 B4 = (lane + 128 < nqb) ? __ldcs(hq4 + lane + 128) : zf;
    float4 A0 = (lane       < nqa) ? __ldcs(ha4 + lane)       : zf;
    float4 A1 = (lane + 32  < nqa) ? __ldcs(ha4 + lane + 32)  : zf;
    float4 A2 = (lane + 64  < nqa) ? __ldcs(ha4 + lane + 64)  : zf;

    TAILFIX(B2, 2, vbb, cb) TAILFIX(B3, 3, vbb, cb) TAILFIX(B4, 4, vbb, cb)
    STEP(B2, Zb, 2) STEP(B3, Zb, 3) STEP(B4, Zb, 4)
    float sumb = (s0 + s1) + (s2 + s3);

    s0 = s1 = s2 = s3 = 0.f;
    TAILFIX(A0, 0, vba, ca) TAILFIX(A1, 1, vba, ca) TAILFIX(A2, 2, vba, ca)
    STEP(A0, Za, 0) STEP(A1, Za, 1) STEP(A2, Za, 2)
    float suma = (s0 + s1) + (s2 + s3);

    #undef STEP
    #undef TAILFIX

    #pragma unroll
    for (int o = 16; o; o >>= 1) {
        suma += __shfl_xor_sync(FULL, suma, o);
        sumb += __shfl_xor_sync(FULL, sumb, o);
    }

    if (lane == 0) {
        float* ob = out + (size_t)b * DIM;
        ob[ia] = zsh[ia] + suma;    // Z_0 is plain z
        ob[ib] = zsh[ib] + sumb;
    }

    // logdet / tail zeroing (d_out is poisoned)
    if (blockIdx.x == 0) {
        const int nfz = (int)(gridDim.x >> 5) * DIM;
        for (int k = nfz + tid; k < out_size; k += THREADS) out[k] = 0.0f;
    }
}

extern "C" void kernel_launch(void* const* d_in, const int* in_sizes, int n_in,
                              void* d_out, int out_size)
{
    const float* z = (const float*)d_in[0];   // [batch, 512]
    const float* h = (const float*)d_in[1];   // [batch, 130816]
    float* out = (float*)d_out;

    const int batch = in_sizes[0] / DIM;      // 256

    dim3 grid(batch * 32);                    // 8192 identical CTAs
    LinearMap_kernel<<<grid, THREADS>>>(z, h, out, out_size);
}

// round 10
// speedup vs baseline: 1.4713x; 1.0042x over previous
#include <cuda_runtime.h>
#include <cuda_bf16.h>
#include <cstdint>

// f_z[b,i] = z[b,i] + sum_{j<i} h[b, i*(i-1)/2 + j] * z[b,j]
// Issue/L1-composite bound: minimize instructions per h-byte at high occ.
//
// Warp handles TWO row pairs (i, 511-i) sequentially (fill amortized, grid
// 4096 = 4.6 waves). h read as aligned-DOWN predicated LDG.128 quads,
// front-batched per pair (MLP 8). z in shared as 4 shifted zero-padded
// copies Z_m[j] = z[j-m]: quad v pairs with ONE aligned LDS.128. Head junk
// hits zero padding; tail junk accumulates and is subtracted post-sum by
// the owning lane (cheap, quads die at pair end).

#define DIM 512
#define HLEN ((DIM * (DIM - 1)) / 2)   // 130816
#define THREADS 256
#define ZPADF 640
#define FULL 0xffffffffu

__device__ __forceinline__ void do_pair(
    const float* __restrict__ hbase, const float* __restrict__ zsh,
    float* __restrict__ ob, int ia, int lane)
{
    const int ib = DIM - 1 - ia;
    const unsigned offa = (unsigned)(ia * (ia - 1) / 2);
    const unsigned offb = (unsigned)(ib * (ib - 1) / 2);
    const int misa = (int)(offa & 3u), misb = (int)(offb & 3u);

    const float4* ha4 = (const float4*)(hbase + (offa & ~3u));
    const float4* hq4 = (const float4*)(hbase + (offb & ~3u));

    const int ea = ia + misa, eb = ib + misb;   // valid elems: [mis, e)
    const int nqa = (ea + 3) >> 2;              // <= 65
    const int nqb = (eb + 3) >> 2;              // 64..129
    const int vba = ea >> 2, ca = ea & 3;
    const int vbb = eb >> 2, cb = eb & 3;

    const float4* Za = (const float4*)(zsh + misa * ZPADF);
    const float4* Zb = (const float4*)(zsh + misb * ZPADF);
    const float4 zf = make_float4(0.f, 0.f, 0.f, 0.f);

    // front-batched loads (steps 0,1 of row b are always full: nqb >= 64)
    float4 B0 = __ldcs(hq4 + lane);
    float4 B1 = __ldcs(hq4 + lane + 32);
    float4 B2 = (lane + 64  < nqb) ? __ldcs(hq4 + lane + 64)  : zf;
    float4 B3 = (lane + 96  < nqb) ? __ldcs(hq4 + lane + 96)  : zf;
    float4 B4 = (lane + 128 < nqb) ? __ldcs(hq4 + lane + 128) : zf;
    float4 A0 = (lane       < nqa) ? __ldcs(ha4 + lane)       : zf;
    float4 A1 = (lane + 32  < nqa) ? __ldcs(ha4 + lane + 32)  : zf;
    float4 A2 = (lane + 64  < nqa) ? __ldcs(ha4 + lane + 64)  : zf;

    float s0 = 0.f, s1 = 0.f, s2 = 0.f, s3 = 0.f;
    #define STEP(Q, Zp, st) {                                   \
        float4 zv = (Zp)[lane + 32 * (st)];                     \
        s0 = fmaf(Q.x, zv.x, s0);                               \
        s1 = fmaf(Q.y, zv.y, s1);                               \
        s2 = fmaf(Q.z, zv.z, s2);                               \
        s3 = fmaf(Q.w, zv.w, s3);                               \
    }
    STEP(B0, Zb, 0) STEP(B1, Zb, 1) STEP(B2, Zb, 2)
    STEP(B3, Zb, 3) STEP(B4, Zb, 4)
    float sumb = (s0 + s1) + (s2 + s3);

    s0 = s1 = s2 = s3 = 0.f;
    STEP(A0, Za, 0) STEP(A1, Za, 1) STEP(A2, Za, 2)
    float suma = (s0 + s1) + (s2 + s3);
    #undef STEP

    // subtract tail-junk products (components k >= c of boundary quad)
    if (cb && lane == (vbb & 31)) {             // vbb>>5 in {2,3,4}
        const int st = vbb >> 5;
        float4 Q = (st == 2) ? B2 : (st == 3) ? B3 : B4;
        float4 zt = Zb[vbb];
        float jnk = Q.w * zt.w;
        if (cb <= 2) jnk = fmaf(Q.z, zt.z, jnk);
        if (cb <= 1) jnk = fmaf(Q.y, zt.y, jnk);
        sumb -= jnk;
    }
    if (ca && lane == (vba & 31)) {             // vba>>5 in {0,1,2}
        const int st = vba >> 5;
        float4 Q = (st == 0) ? A0 : (st == 1) ? A1 : A2;
        float4 zt = Za[vba];
        float jnk = Q.w * zt.w;
        if (ca <= 2) jnk = fmaf(Q.z, zt.z, jnk);
        if (ca <= 1) jnk = fmaf(Q.y, zt.y, jnk);
        suma -= jnk;
    }

    #pragma unroll
    for (int o = 16; o; o >>= 1) {
        suma += __shfl_xor_sync(FULL, suma, o);
        sumb += __shfl_xor_sync(FULL, sumb, o);
    }

    if (lane == 0) {
        ob[ia] = zsh[ia] + suma;    // Z_0 is plain z
        ob[ib] = zsh[ib] + sumb;
    }
}

__global__ __launch_bounds__(THREADS, 6) void LinearMap_kernel(
    const float* __restrict__ z,
    const float* __restrict__ h,
    float* __restrict__ out,
    int out_size)
{
    __shared__ float zsh[4 * ZPADF];    // copy m at m*ZPADF

    const int b    = blockIdx.x >> 4;   // / 16
    const int cg   = blockIdx.x & 15;   // pair-group within batch
    const int tid  = threadIdx.x;
    const int warp = tid >> 5;
    const int lane = tid & 31;

    // zero pad regions ([512,640) per copy; heads [0,m))
    {
        int m = tid >> 6;               // 0..3
        int j = 512 + (tid & 63);
        zsh[m * ZPADF + j]      = 0.f;
        zsh[m * ZPADF + j + 64] = 0.f;
        if (tid < 16) {
            int mm = tid >> 2, k = tid & 3;
            if (k < mm) zsh[mm * ZPADF + k] = 0.f;
        }
    }
    __syncthreads();
    // data into all 4 shifted copies
    {
        const float* zb = z + (size_t)b * DIM;
        #pragma unroll
        for (int j = tid; j < DIM; j += THREADS) {
            float v = zb[j];
            zsh[j]                 = v;
            zsh[ZPADF     + j + 1] = v;
            zsh[2 * ZPADF + j + 2] = v;
            zsh[3 * ZPADF + j + 3] = v;
        }
    }
    __syncthreads();

    const float* hbase = h + (size_t)b * HLEN;
    float* ob = out + (size_t)b * DIM;
    const int base = cg * 16;                   // 16 pairs per CTA

    do_pair(hbase, zsh, ob, base + warp,     lane);
    do_pair(hbase, zsh, ob, base + 8 + warp, lane);

    // logdet / tail zeroing (d_out is poisoned)
    if (blockIdx.x == 0) {
        const int nfz = (int)(gridDim.x >> 4) * DIM;
        for (int k = nfz + tid; k < out_size; k += THREADS) out[k] = 0.0f;
    }
}

extern "C" void kernel_launch(void* const* d_in, const int* in_sizes, int n_in,
                              void* d_out, int out_size)
{
    const float* z = (const float*)d_in[0];   // [batch, 512]
    const float* h = (const float*)d_in[1];   // [batch, 130816]
    float* out = (float*)d_out;

    const int batch = in_sizes[0] / DIM;      // 256

    dim3 grid(batch * 16);                    // 4096 identical CTAs
    LinearMap_kernel<<<grid, THREADS>>>(z, h, out, out_size);
}

// round 11
// speedup vs baseline: 1.5697x; 1.0669x over previous
#include <cuda_runtime.h>
#include <cuda_bf16.h>
#include <cstdint>

// f_z[b,i] = z[b,i] + sum_{j<i} h[b, i*(i-1)/2 + j] * z[b,j]
// Wall = l1tex wavefronts (LDG + per-quad LDS). Fix: pair rows (i, 513-i),
// which provably share off%4 (mis class m), so one register set
// zq[r] = Z_m[4*(lane+32r)..+3] serves BOTH rows with the lane's OWN
// registers -- no per-quad LDS, no shfl. Z_m are zero-padded shifted smem
// copies (head junk hits zeros); tail junk subtracted post-sum from regs.
// Leftover rows: warp1 -> (257,256) [mis 0], warp0 -> rows 0,1 (trivial).

#define DIM 512
#define HLEN ((DIM * (DIM - 1)) / 2)   // 130816
#define THREADS 256
#define ZPADF 640
#define FULL 0xffffffffu

// ia: short row (len <= 257, a-path 3 steps). ib: long row (256..511, b-path
// 5 steps). Requires off(ia)%4 == off(ib)%4.
__device__ __forceinline__ void do_pair(
    const float* __restrict__ hbase, const float* __restrict__ zsh,
    float* __restrict__ ob, int ia, int ib, int lane)
{
    const unsigned offa = (unsigned)(ia * (ia - 1) / 2);
    const unsigned offb = (unsigned)(ib * (ib - 1) / 2);
    const int m = (int)(offa & 3u);            // == offb & 3

    const float4* ha4 = (const float4*)(hbase + (offa & ~3u));
    const float4* hb4 = (const float4*)(hbase + (offb & ~3u));

    const int ea = ia + m, eb = ib + m;        // valid padded elems: [m, e)
    const int nqa = (ea + 3) >> 2;             // <= 65
    const int nqb = (eb + 3) >> 2;             // 64..129
    const int vba = ea >> 2, ca = ea & 3;
    const int vbb = eb >> 2, cb = eb & 3;

    const float4 zf = make_float4(0.f, 0.f, 0.f, 0.f);

    // h loads, front-batched (steps 0,1 of b always full: nqb >= 64)
    float4 B0 = __ldcs(hb4 + lane);
    float4 B1 = __ldcs(hb4 + lane + 32);
    float4 B2 = (lane + 64  < nqb) ? __ldcs(hb4 + lane + 64)  : zf;
    float4 B3 = (lane + 96  < nqb) ? __ldcs(hb4 + lane + 96)  : zf;
    float4 B4 = (lane + 128 < nqb) ? __ldcs(hb4 + lane + 128) : zf;
    float4 A0 = (lane       < nqa) ? __ldcs(ha4 + lane)       : zf;
    float4 A1 = (lane + 32  < nqa) ? __ldcs(ha4 + lane + 32)  : zf;
    float4 A2 = (lane + 64  < nqa) ? __ldcs(ha4 + lane + 64)  : zf;

    // z registers for this mis class (one-time; overlaps the LDGs above)
    const float4* Zm4 = (const float4*)(zsh + m * ZPADF);
    float4 zq0 = Zm4[lane];
    float4 zq1 = Zm4[lane + 32];
    float4 zq2 = Zm4[lane + 64];
    float4 zq3 = Zm4[lane + 96];
    float4 zq4 = Zm4[lane + 128];

    float s0 = 0.f, s1 = 0.f, s2 = 0.f, s3 = 0.f;
    #define STEP(Q, ZV) {                                       \
        s0 = fmaf(Q.x, ZV.x, s0);                               \
        s1 = fmaf(Q.y, ZV.y, s1);                               \
        s2 = fmaf(Q.z, ZV.z, s2);                               \
        s3 = fmaf(Q.w, ZV.w, s3);                               \
    }
    STEP(B0, zq0) STEP(B1, zq1) STEP(B2, zq2)
    STEP(B3, zq3) STEP(B4, zq4)
    float sumb = (s0 + s1) + (s2 + s3);

    s0 = s1 = s2 = s3 = 0.f;
    STEP(A0, zq0) STEP(A1, zq1) STEP(A2, zq2)
    float suma = (s0 + s1) + (s2 + s3);
    #undef STEP

    // tail-junk subtract (components k >= c of boundary quad), all from regs
    if (cb && lane == (vbb & 31)) {             // vbb>>5 in {2,3,4}
        const int st = vbb >> 5;
        float4 Q  = (st == 2) ? B2  : (st == 3) ? B3  : B4;
        float4 zt = (st == 2) ? zq2 : (st == 3) ? zq3 : zq4;
        float jnk = Q.w * zt.w;
        if (cb <= 2) jnk = fmaf(Q.z, zt.z, jnk);
        if (cb <= 1) jnk = fmaf(Q.y, zt.y, jnk);
        sumb -= jnk;
    }
    if (ca && lane == (vba & 31)) {             // vba>>5 in {0,1,2}
        const int st = vba >> 5;
        float4 Q  = (st == 0) ? A0  : (st == 1) ? A1  : A2;
        float4 zt = (st == 0) ? zq0 : (st == 1) ? zq1 : zq2;
        float jnk = Q.w * zt.w;
        if (ca <= 2) jnk = fmaf(Q.z, zt.z, jnk);
        if (ca <= 1) jnk = fmaf(Q.y, zt.y, jnk);
        suma -= jnk;
    }

    #pragma unroll
    for (int o = 16; o; o >>= 1) {
        suma += __shfl_xor_sync(FULL, suma, o);
        sumb += __shfl_xor_sync(FULL, sumb, o);
    }

    if (lane == 0) {
        ob[ia] = zsh[ia] + suma;    // Z_0 is plain z
        ob[ib] = zsh[ib] + sumb;
    }
}

__device__ __forceinline__ void do_work(
    const float* __restrict__ hbase, const float* __restrict__ zsh,
    float* __restrict__ ob, int w, int lane)
{
    if (w >= 2)      do_pair(hbase, zsh, ob, w, 513 - w, lane);
    else if (w == 1) do_pair(hbase, zsh, ob, 257, 256, lane);
    else if (lane == 0) {                      // rows 0, 1
        ob[0] = zsh[0];
        ob[1] = zsh[1] + hbase[0] * zsh[0];
    }
}

__global__ __launch_bounds__(THREADS, 4) void LinearMap_kernel(
    const float* __restrict__ z,
    const float* __restrict__ h,
    float* __restrict__ out,
    int out_size)
{
    __shared__ float zsh[4 * ZPADF];    // shifted copy m at m*ZPADF

    const int b    = blockIdx.x >> 4;   // / 16
    const int cg   = blockIdx.x & 15;
    const int tid  = threadIdx.x;
    const int warp = tid >> 5;
    const int lane = tid & 31;

    // zero pad regions ([512,640) per copy; heads [0,m))
    {
        int m = tid >> 6;               // 0..3
        int j = 512 + (tid & 63);
        zsh[m * ZPADF + j]      = 0.f;
        zsh[m * ZPADF + j + 64] = 0.f;
        if (tid < 16) {
            int mm = tid >> 2, k = tid & 3;
            if (k < mm) zsh[mm * ZPADF + k] = 0.f;
        }
    }
    __syncthreads();
    // data into all 4 shifted copies: Z_m[j+m] = z[j]
    {
        const float* zb = z + (size_t)b * DIM;
        #pragma unroll
        for (int j = tid; j < DIM; j += THREADS) {
            float v = zb[j];
            zsh[j]                 = v;
            zsh[ZPADF     + j + 1] = v;
            zsh[2 * ZPADF + j + 2] = v;
            zsh[3 * ZPADF + j + 3] = v;
        }
    }
    __syncthreads();

    const float* hbase = h + (size_t)b * HLEN;
    float* ob = out + (size_t)b * DIM;
    const int base = cg * 16;                   // 16 work units per CTA

    do_work(hbase, zsh, ob, base + warp,     lane);
    do_work(hbase, zsh, ob, base + 8 + warp, lane);

    // logdet / tail zeroing (d_out is poisoned)
    if (blockIdx.x == 0) {
        const int nfz = (int)(gridDim.x >> 4) * DIM;
        for (int k = nfz + tid; k < out_size; k += THREADS) out[k] = 0.0f;
    }
}

extern "C" void kernel_launch(void* const* d_in, const int* in_sizes, int n_in,
                              void* d_out, int out_size)
{
    const float* z = (const float*)d_in[0];   // [batch, 512]
    const float* h = (const float*)d_in[1];   // [batch, 130816]
    float* out = (float*)d_out;

    const int batch = in_sizes[0] / DIM;      // 256

    dim3 grid(batch * 16);                    // 4096 identical CTAs
    LinearMap_kernel<<<grid, THREADS>>>(z, h, out, out_size);
}